// round 4
// baseline (speedup 1.0000x reference)
#include <cuda_runtime.h>
#include <cfloat>

#define B_  2
#define T_  2048
#define C_  768
#define H_  12
#define HD_ 64
#define BH_ (B_*H_)

// ln(2048)/sqrt(64)
#define QSC 0.9530773732699245f

// scratch (static device globals; no allocs allowed)
__device__ float g_q[(size_t)BH_*HD_*T_];   // [bh][d][t], pre-scaled by QSC*qm[d]
__device__ float g_k[(size_t)BH_*HD_*T_];   // [bh][d][t]
__device__ float g_v[(size_t)BH_*T_*HD_];   // [bh][t][d]
__device__ float g_y[(size_t)B_*T_*C_];     // [b][t][h*HD]

// ---------------------------------------------------------------------------
// cp.async helpers
// ---------------------------------------------------------------------------
__device__ __forceinline__ void cpa16(void* dst, const void* src) {
    unsigned s = (unsigned)__cvta_generic_to_shared(dst);
    asm volatile("cp.async.cg.shared.global [%0], [%1], 16;\n" :: "r"(s), "l"(src));
}
__device__ __forceinline__ void cpa_commit() {
    asm volatile("cp.async.commit_group;\n");
}
template<int N> __device__ __forceinline__ void cpa_wait() {
    asm volatile("cp.async.wait_group %0;\n" :: "n"(N));
}

// ---------------------------------------------------------------------------
// GEMM: C[4096,768] = A[4096,768] @ W[768,768], 64x128 tiles, BK=32,
// cp.async double-buffered, conflict-free float2 B-fragments.
// 256 threads, 4x8 micro-tile. mode: 0=q(transposed+scaled), 1=k(transposed),
// 2=v(row), 3=proj(plain write to outp, A:=g_y).
// ---------------------------------------------------------------------------
#define GBM 64
#define GBN 128
#define GBK 32

__global__ __launch_bounds__(256)
void gemm64(const float* __restrict__ Asrc,
            const float* __restrict__ W0, const float* __restrict__ W1,
            const float* __restrict__ W2, const float* __restrict__ qm,
            float* __restrict__ outp, int proj)
{
    __shared__ float As[2][GBM][GBK];   // 16 KB
    __shared__ float Bs[2][GBK][GBN];   // 32 KB

    int mode = proj ? 3 : blockIdx.z;
    const float* W = (mode == 1) ? W1 : (mode == 2 ? W2 : W0);
    const float* A = proj ? (const float*)g_y : Asrc;

    int tid  = threadIdx.x;
    int row0 = blockIdx.y * GBM;
    int col0 = blockIdx.x * GBN;

    int ar = tid >> 2, ac = (tid & 3) * 8;     // A tile: 64 x 32
    int br = tid >> 3, bc = (tid & 7) * 16;    // B tile: 32 x 128
    int ty = tid >> 4, tx = tid & 15;

    // preload k-slice 0
    cpa16(&As[0][ar][ac],   &A[(size_t)(row0 + ar)*C_ + ac]);
    cpa16(&As[0][ar][ac+4], &A[(size_t)(row0 + ar)*C_ + ac + 4]);
#pragma unroll
    for (int u = 0; u < 4; u++)
        cpa16(&Bs[0][br][bc + u*4], &W[(size_t)br*C_ + col0 + bc + u*4]);
    cpa_commit();

    float acc[4][8];
#pragma unroll
    for (int i = 0; i < 4; i++)
#pragma unroll
        for (int j = 0; j < 8; j++) acc[i][j] = 0.f;

    const int NIT = C_ / GBK;    // 24
    for (int it = 0; it < NIT; it++) {
        if (it + 1 < NIT) {
            int nb = (it + 1) & 1;
            int k0 = (it + 1) * GBK;
            cpa16(&As[nb][ar][ac],   &A[(size_t)(row0 + ar)*C_ + k0 + ac]);
            cpa16(&As[nb][ar][ac+4], &A[(size_t)(row0 + ar)*C_ + k0 + ac + 4]);
#pragma unroll
            for (int u = 0; u < 4; u++)
                cpa16(&Bs[nb][br][bc + u*4], &W[(size_t)(k0 + br)*C_ + col0 + bc + u*4]);
            cpa_commit();
            cpa_wait<1>();
        } else {
            cpa_wait<0>();
        }
        __syncthreads();

        int cb = it & 1;
#pragma unroll
        for (int kb = 0; kb < 8; kb++) {
            float a_[4][4];
            *(float4*)a_[0] = *(const float4*)&As[cb][ty*4+0][kb*4];
            *(float4*)a_[1] = *(const float4*)&As[cb][ty*4+1][kb*4];
            *(float4*)a_[2] = *(const float4*)&As[cb][ty*4+2][kb*4];
            *(float4*)a_[3] = *(const float4*)&As[cb][ty*4+3][kb*4];
#pragma unroll
            for (int kl = 0; kl < 4; kl++) {
                const float* brow = &Bs[cb][kb*4+kl][0];
                float2 b0 = *(const float2*)&brow[tx*2];
                float2 b1 = *(const float2*)&brow[tx*2 + 32];
                float2 b2 = *(const float2*)&brow[tx*2 + 64];
                float2 b3 = *(const float2*)&brow[tx*2 + 96];
#pragma unroll
                for (int i = 0; i < 4; i++) {
                    float av = a_[i][kl];
                    acc[i][0] += av*b0.x; acc[i][1] += av*b0.y;
                    acc[i][2] += av*b1.x; acc[i][3] += av*b1.y;
                    acc[i][4] += av*b2.x; acc[i][5] += av*b2.y;
                    acc[i][6] += av*b3.x; acc[i][7] += av*b3.y;
                }
            }
        }
        __syncthreads();
    }

    // epilogue: rows m0..m0+3; cols col0 + g*32 + tx*2 + e  <->  acc[i][g*2+e]
    int m0 = row0 + ty*4;
    if (mode == 3) {
#pragma unroll
        for (int i = 0; i < 4; i++) {
            float* dst = &outp[(size_t)(m0 + i)*C_ + col0 + tx*2];
            *(float2*)(dst)      = make_float2(acc[i][0], acc[i][1]);
            *(float2*)(dst + 32) = make_float2(acc[i][2], acc[i][3]);
            *(float2*)(dst + 64) = make_float2(acc[i][4], acc[i][5]);
            *(float2*)(dst + 96) = make_float2(acc[i][6], acc[i][7]);
        }
    } else {
        int b  = m0 >> 11, t0 = m0 & (T_-1);
        int h0 = col0 >> 6;
        if (mode == 2) {
#pragma unroll
            for (int i = 0; i < 4; i++) {
#pragma unroll
                for (int g = 0; g < 4; g++) {
                    int h = h0 + (g >> 1);
                    int d = (g & 1)*32 + tx*2;
                    *(float2*)&g_v[((size_t)(b*H_ + h)*T_ + (t0+i))*HD_ + d] =
                        make_float2(acc[i][g*2], acc[i][g*2+1]);
                }
            }
        } else {
            float* dstb = (mode == 0) ? g_q : g_k;
#pragma unroll
            for (int g = 0; g < 4; g++) {
                int h = h0 + (g >> 1);
                size_t base = (size_t)(b*H_ + h)*HD_*T_;
#pragma unroll
                for (int e = 0; e < 2; e++) {
                    int d = (g & 1)*32 + tx*2 + e;
                    float sc = (mode == 0) ? QSC * __ldg(&qm[d]) : 1.f;
                    *(float4*)&dstb[base + (size_t)d*T_ + t0] =
                        make_float4(acc[0][g*2+e]*sc, acc[1][g*2+e]*sc,
                                    acc[2][g*2+e]*sc, acc[3][g*2+e]*sc);
                }
            }
        }
    }
}

// ---------------------------------------------------------------------------
// GEMM-tiled sparse top-4 causal attention.
// CTA: 64 queries x K tiles of 128. 256 threads = 16 qrow x 16 kcol,
// micro-tile 4q x 8k (float2 K-fragments, conflict-free). Per-thread top-4
// over its key slice; smem merge; V gather weighted by tanh.
// Dynamic smem (80 KB), cp.async double-buffered K.
// ---------------------------------------------------------------------------
#define MQ 64
#define NK 128

struct AttnSmem {
    union {
        struct { float Qs[64][64]; float Ks[2][64][NK]; } t;   // 80 KB
        struct { float cv[64][65]; int ci[64][65];
                 float ws[64][4];  int is[64][4]; } c;
    } u;
};

extern __shared__ char dyn_smem[];

#define INS4(W0,W1,W2,W3,I0,I1,I2,I3,s,j)                                   \
    if ((s) > W3) { W3=(s); I3=(j);                                         \
        if (W3>W2){float tf_=W2;W2=W3;W3=tf_;int ti_=I2;I2=I3;I3=ti_;       \
            if (W2>W1){tf_=W1;W1=W2;W2=tf_;ti_=I1;I1=I2;I2=ti_;             \
                if (W1>W0){tf_=W0;W0=W1;W1=tf_;ti_=I0;I0=I1;I1=ti_;}}}}

__global__ __launch_bounds__(256)
void attn_kernel()
{
    AttnSmem& sm = *reinterpret_cast<AttnSmem*>(dyn_smem);
    int bh  = blockIdx.y;
    int q0  = (gridDim.x - 1 - blockIdx.x) * MQ;   // heavy CTAs first
    int tid = threadIdx.x;
    int qrow = tid >> 4;     // 0..15
    int kcol = tid & 15;     // 0..15

    const float* qb = g_q + (size_t)bh*HD_*T_;
    const float* kb = g_k + (size_t)bh*HD_*T_;
    const float* vb = g_v + (size_t)bh*T_*HD_;

    int lr  = tid >> 2;            // 0..63 (= d)
    int lcq = (tid & 3) * 16;      // Q cols
    int lck = (tid & 3) * 32;      // K cols

    // preload Q tile + K tile 0 (one cp.async group)
#pragma unroll
    for (int u = 0; u < 4; u++)
        cpa16(&sm.u.t.Qs[lr][lcq + u*4], qb + (size_t)lr*T_ + q0 + lcq + u*4);
#pragma unroll
    for (int u = 0; u < 8; u++)
        cpa16(&sm.u.t.Ks[0][lr][lck + u*4], kb + (size_t)lr*T_ + lck + u*4);
    cpa_commit();

    float w[4][4];
    int  id[4][4];
#pragma unroll
    for (int u = 0; u < 4; u++)
#pragma unroll
        for (int m = 0; m < 4; m++) { w[u][m] = -FLT_MAX; id[u][m] = 0; }

    const int ntiles = q0/NK + 1;
    for (int tile = 0; tile < ntiles; tile++) {
        if (tile + 1 < ntiles) {
            int nb = (tile + 1) & 1;
            const float* src = kb + (size_t)lr*T_ + (tile+1)*NK + lck;
#pragma unroll
            for (int u = 0; u < 8; u++)
                cpa16(&sm.u.t.Ks[nb][lr][lck + u*4], src + u*4);
            cpa_commit();
            cpa_wait<1>();
        } else {
            cpa_wait<0>();
        }
        __syncthreads();

        int cb = tile & 1;
        float accv[4][8];
#pragma unroll
        for (int u = 0; u < 4; u++)
#pragma unroll
            for (int v = 0; v < 8; v++) accv[u][v] = 0.f;

#pragma unroll 8
        for (int kk = 0; kk < 64; kk++) {
            float4 av = *(const float4*)&sm.u.t.Qs[kk][qrow*4];
            const float* krow = &sm.u.t.Ks[cb][kk][0];
            float2 b0 = *(const float2*)&krow[kcol*2];
            float2 b1 = *(const float2*)&krow[kcol*2 + 32];
            float2 b2 = *(const float2*)&krow[kcol*2 + 64];
            float2 b3 = *(const float2*)&krow[kcol*2 + 96];
            float aa[4] = {av.x, av.y, av.z, av.w};
            float bb[8] = {b0.x,b0.y,b1.x,b1.y,b2.x,b2.y,b3.x,b3.y};
#pragma unroll
            for (int u = 0; u < 4; u++)
#pragma unroll
                for (int v = 0; v < 8; v++)
                    accv[u][v] += aa[u]*bb[v];
        }

        int jb = tile*NK;
        if (tile == ntiles-1) {
#pragma unroll
            for (int u = 0; u < 4; u++) {
                int qg = q0 + qrow*4 + u;
#pragma unroll
                for (int v = 0; v < 8; v++) {
                    float s = accv[u][v];
                    int j = jb + ((v >> 1) << 5) + kcol*2 + (v & 1);
                    if (j <= qg) { INS4(w[u][0],w[u][1],w[u][2],w[u][3],
                                        id[u][0],id[u][1],id[u][2],id[u][3], s, j); }
                }
            }
        } else {
#pragma unroll
            for (int u = 0; u < 4; u++) {
#pragma unroll
                for (int v = 0; v < 8; v++) {
                    float s = accv[u][v];
                    int j = jb + ((v >> 1) << 5) + kcol*2 + (v & 1);
                    INS4(w[u][0],w[u][1],w[u][2],w[u][3],
                         id[u][0],id[u][1],id[u][2],id[u][3], s, j);
                }
            }
        }
        __syncthreads();
    }

    // write per-thread candidates: cand[kcol*4+m][qrow*4+u]
#pragma unroll
    for (int u = 0; u < 4; u++) {
        int q = qrow*4 + u;
#pragma unroll
        for (int m = 0; m < 4; m++) {
            int c = kcol*4 + m;
            sm.u.c.cv[c][q] = w[u][m];
            sm.u.c.ci[c][q] = id[u][m];
        }
    }
    __syncthreads();

    if (tid < 64) {
        int q = tid, qi = q0 + q;
        float m0=-FLT_MAX, m1=-FLT_MAX, m2=-FLT_MAX, m3=-FLT_MAX;
        int   j0_=0, j1_=0, j2_=0, j3_=0;
        for (int c = 0; c < 64; c++) {
            float s = sm.u.c.cv[c][q];
            int   j = sm.u.c.ci[c][q];
            INS4(m0,m1,m2,m3,j0_,j1_,j2_,j3_, s, j);
        }
        // kth = 4th largest of (causal scores U (T-1-i) masked zeros)
        int z  = T_ - 1 - qi;
        int nz = z < 4 ? z : 4;
        int p  = (m0 > 0.f) + (m1 > 0.f) + (m2 > 0.f) + (m3 > 0.f);
        float kth;
        if (p >= 4)            kth = m3;
        else if (p + nz >= 4)  kth = 0.f;
        else kth = (nz == 0) ? m3 : (nz == 1 ? m2 : (nz == 2 ? m1 : m0));

        sm.u.c.ws[q][0] = (m0 >= kth) ? tanhf(m0) : 0.f;  sm.u.c.is[q][0] = j0_;
        sm.u.c.ws[q][1] = (m1 >= kth) ? tanhf(m1) : 0.f;  sm.u.c.is[q][1] = j1_;
        sm.u.c.ws[q][2] = (m2 >= kth) ? tanhf(m2) : 0.f;  sm.u.c.is[q][2] = j2_;
        sm.u.c.ws[q][3] = (m3 >= kth) ? tanhf(m3) : 0.f;  sm.u.c.is[q][3] = j3_;
    }
    __syncthreads();

    // V gather + Y write: thread = (q, 16-dim group)
    {
        int q = tid >> 2, g = tid & 3;
        float4 a0 = make_float4(0,0,0,0), a1 = a0, a2 = a0, a3 = a0;
#pragma unroll
        for (int m = 0; m < 4; m++) {
            float wt = sm.u.c.ws[q][m];
            const float4* vp = (const float4*)(vb + (size_t)sm.u.c.is[q][m]*HD_ + g*16);
            float4 v0 = vp[0], v1 = vp[1], v2 = vp[2], v3 = vp[3];
            a0.x += wt*v0.x; a0.y += wt*v0.y; a0.z += wt*v0.z; a0.w += wt*v0.w;
            a1.x += wt*v1.x; a1.y += wt*v1.y; a1.z += wt*v1.z; a1.w += wt*v1.w;
            a2.x += wt*v2.x; a2.y += wt*v2.y; a2.z += wt*v2.z; a2.w += wt*v2.w;
            a3.x += wt*v3.x; a3.y += wt*v3.y; a3.z += wt*v3.z; a3.w += wt*v3.w;
        }
        int b = bh / H_, h = bh % H_;
        float4* yp = (float4*)(g_y + ((size_t)b*T_ + q0 + q)*C_ + h*HD_ + g*16);
        yp[0] = a0; yp[1] = a1; yp[2] = a2; yp[3] = a3;
    }
}

// ---------------------------------------------------------------------------
extern "C" void kernel_launch(void* const* d_in, const int* in_sizes, int n_in,
                              void* d_out, int out_size)
{
    const float* x  = (const float*)d_in[0];
    const float* Wq = (const float*)d_in[1];
    const float* Wk = (const float*)d_in[2];
    const float* Wv = (const float*)d_in[3];
    const float* Wp = (const float*)d_in[4];
    const float* qm = (const float*)d_in[5];
    float* out = (float*)d_out;

    cudaFuncSetAttribute(attn_kernel,
                         cudaFuncAttributeMaxDynamicSharedMemorySize,
                         (int)sizeof(AttnSmem));

    gemm64<<<dim3(C_/GBN, (B_*T_)/GBM, 3), 256>>>(x, Wq, Wk, Wv, qm, nullptr, 0);
    attn_kernel<<<dim3(T_/MQ, BH_), 256, sizeof(AttnSmem)>>>();
    gemm64<<<dim3(C_/GBN, (B_*T_)/GBM, 1), 256>>>(nullptr, Wp, nullptr, nullptr, nullptr, out, 1);
}